// round 16
// baseline (speedup 1.0000x reference)
#include <cuda_runtime.h>
#include <cstdint>
#include <cstddef>

// ===========================================================================
// SpikingMLP hybrid (proven-numerics): fc1 = fp32 FFMA GEMM with Round-1's
// exact loop body (reference-correlated rounding, 2 CTAs/SM), fc2 = exact
// int8 IMMA on base-256 digit planes of w2. T=4 B=16 N=1024 C=512 H=2048.
// ===========================================================================

namespace {
constexpr int T_ = 4, B_ = 16, N_ = 1024, C_ = 512, H_ = 2048;
constexpr int M_    = T_ * B_ * N_;   // 65536
constexpr int ROWS_ = B_ * N_;        // 16384
constexpr int RB_   = 64;
constexpr float EPS_ = 1e-5f;
__host__ __device__ constexpr uint32_t pmask(uint32_t v, int np) {
    uint32_t m = 0;
    for (int i = 0; i < np; ++i) m |= 1u << ((v >> (4 * i)) & 15);
    return m;
}
}

// ----------------------------- scratch ------------------------------------
__device__ __align__(256) float  g_y[(size_t)M_ * H_];
__device__ __align__(256) float  g_z[(size_t)M_ * C_];
__device__ __align__(256) int8_t g_sp[(size_t)M_ * H_];
__device__ __align__(256) int8_t g_w2p[4][(size_t)C_ * H_];
__device__ float g_p1s[RB_ * H_], g_p1q[RB_ * H_];
__device__ float g_p2s[RB_ * C_], g_p2q[RB_ * C_];
__device__ float g_mean1[H_], g_sc1[H_], g_mean2[C_], g_sc2[C_];

// ----------------------------- PTX helpers --------------------------------
__device__ __forceinline__ uint32_t smem_u32(const void* p) {
    uint32_t a;
    asm("{ .reg .u64 t; cvta.to.shared.u64 t, %1; cvt.u32.u64 %0, t; }" : "=r"(a) : "l"(p));
    return a;
}
__device__ __forceinline__ void cp_async16(uint32_t s, const void* g) {
    asm volatile("cp.async.cg.shared.global [%0], [%1], 16;" :: "r"(s), "l"(g) : "memory");
}
__device__ __forceinline__ void cp_commit() {
    asm volatile("cp.async.commit_group;" ::: "memory");
}
template <int N_PEND>
__device__ __forceinline__ void cp_wait() {
    asm volatile("cp.async.wait_group %0;" :: "n"(N_PEND) : "memory");
}
__device__ __forceinline__ void ldsm4(uint32_t* r, uint32_t a) {
    asm volatile("ldmatrix.sync.aligned.m8n8.x4.shared.b16 {%0,%1,%2,%3}, [%4];"
                 : "=r"(r[0]), "=r"(r[1]), "=r"(r[2]), "=r"(r[3]) : "r"(a) : "memory");
}
__device__ __forceinline__ void mma_s8(int* c, const uint32_t* a, const uint32_t* b) {
    asm volatile(
        "mma.sync.aligned.m16n8k32.row.col.s32.s8.s8.s32 "
        "{%0,%1,%2,%3}, {%4,%5,%6,%7}, {%8,%9}, {%0,%1,%2,%3};"
        : "+r"(c[0]), "+r"(c[1]), "+r"(c[2]), "+r"(c[3])
        : "r"(a[0]), "r"(a[1]), "r"(a[2]), "r"(a[3]), "r"(b[0]), "r"(b[1]));
}
__device__ __forceinline__ uint32_t sw64(int row, int c16) {
    return (uint32_t)(row * 64 + ((((c16) + (row >> 1)) & 3) << 4));
}

// ---------------------------------------------------------------------------
// fp32 SGEMM (fc1) — Round-1's exact kernel body (measured 54.7% fma,
// rel_err 5.64e-4): static smem, LDG->transposed STS per chunk, k-ascending
// FFMA chain per output element, acc + bias epilogue. 2 CTAs/SM.
// ---------------------------------------------------------------------------
template <int K, int NOUT>
__global__ __launch_bounds__(256) void sgemm_f32(
    const float* __restrict__ A, const float* __restrict__ Bw,
    const float* __restrict__ bias, float* __restrict__ Cout)
{
    __shared__ float As[16][128];
    __shared__ float Bs[16][128];

    const int tid = threadIdx.x;
    const int tx = tid & 15;
    const int ty = tid >> 4;
    const int n0 = blockIdx.x * 128;
    const int m0 = blockIdx.y * 128;

    const float* Ap = A + (size_t)m0 * K;
    const float* Bp = Bw + (size_t)n0 * K;

    float acc[8][8];
#pragma unroll
    for (int i = 0; i < 8; ++i)
#pragma unroll
        for (int j = 0; j < 8; ++j) acc[i][j] = 0.f;

    for (int k0 = 0; k0 < K; k0 += 16) {
#pragma unroll
        for (int it = 0; it < 2; ++it) {
            int idx = tid + it * 256;
            int row = idx >> 2;          // 0..127
            int kq  = (idx & 3) << 2;    // 0,4,8,12
            float4 av = *reinterpret_cast<const float4*>(Ap + (size_t)row * K + k0 + kq);
            As[kq + 0][row] = av.x; As[kq + 1][row] = av.y;
            As[kq + 2][row] = av.z; As[kq + 3][row] = av.w;
            float4 bv = *reinterpret_cast<const float4*>(Bp + (size_t)row * K + k0 + kq);
            Bs[kq + 0][row] = bv.x; Bs[kq + 1][row] = bv.y;
            Bs[kq + 2][row] = bv.z; Bs[kq + 3][row] = bv.w;
        }
        __syncthreads();
#pragma unroll
        for (int k = 0; k < 16; ++k) {
            float a[8], b[8];
            *reinterpret_cast<float4*>(a)     = *reinterpret_cast<const float4*>(&As[k][ty * 8]);
            *reinterpret_cast<float4*>(a + 4) = *reinterpret_cast<const float4*>(&As[k][ty * 8 + 4]);
            *reinterpret_cast<float4*>(b)     = *reinterpret_cast<const float4*>(&Bs[k][tx * 8]);
            *reinterpret_cast<float4*>(b + 4) = *reinterpret_cast<const float4*>(&Bs[k][tx * 8 + 4]);
#pragma unroll
            for (int i = 0; i < 8; ++i)
#pragma unroll
                for (int j = 0; j < 8; ++j)
                    acc[i][j] += a[i] * b[j];
        }
        __syncthreads();
    }

    float bvals[8];
#pragma unroll
    for (int j = 0; j < 8; ++j) bvals[j] = bias[n0 + tx * 8 + j];

#pragma unroll
    for (int i = 0; i < 8; ++i) {
        float rowv[8];
#pragma unroll
        for (int j = 0; j < 8; ++j) rowv[j] = acc[i][j] + bvals[j];
        float* outp = Cout + (size_t)(m0 + ty * 8 + i) * NOUT + n0 + tx * 8;
        *reinterpret_cast<float4*>(outp)     = make_float4(rowv[0], rowv[1], rowv[2], rowv[3]);
        *reinterpret_cast<float4*>(outp + 4) = make_float4(rowv[4], rowv[5], rowv[6], rowv[7]);
    }
}

// ---------------------------------------------------------------------------
// Digitize w2: v = rn(w*2^31), balanced base-256 digits d0..d3 (exact).
// ---------------------------------------------------------------------------
__global__ void digitize_kernel(const float* __restrict__ src, size_t n, float scale,
                                int8_t* __restrict__ p0, int8_t* __restrict__ p1,
                                int8_t* __restrict__ p2, int8_t* __restrict__ p3)
{
    for (size_t i = (size_t)blockIdx.x * blockDim.x + threadIdx.x; i < n;
         i += (size_t)gridDim.x * blockDim.x) {
        int v = __float2int_rn(src[i] * scale);
        int d3 = ((v + 128) & 255) - 128; v = (v - d3) >> 8;
        int d2 = ((v + 128) & 255) - 128; v = (v - d2) >> 8;
        int d1 = ((v + 128) & 255) - 128; v = (v - d1) >> 8;
        p0[i] = (int8_t)v;  p1[i] = (int8_t)d1;
        p2[i] = (int8_t)d2; p3[i] = (int8_t)d3;
    }
}

// ---------------------------------------------------------------------------
// Exact s8 IMMA GEMM pass (fc2). Pair list in PAS/PBS/GRS nibbles.
// Two s32 accumulator groups over full K; epilogue r = S0*sc0 + S1*sc1
// (+bias | += out). CTA 128x128, chunk K=64, 8 warps 2x4, double-buffered
// cp.async, SW64 swizzle, 8 smem plane slots.
// ---------------------------------------------------------------------------
template <uint32_t PAS, uint32_t PBS, uint32_t GRS, int NP, int K, int NOUT, bool ACCUM>
__global__ __launch_bounds__(256, 1) void gemm_i8(
    const int8_t* __restrict__ a0, const int8_t* __restrict__ a1,
    const int8_t* __restrict__ a2, const int8_t* __restrict__ a3,
    const int8_t* __restrict__ b0, const int8_t* __restrict__ b1,
    const int8_t* __restrict__ b2, const int8_t* __restrict__ b3,
    const float* __restrict__ bias, float* __restrict__ Cout,
    float sc0, float sc1)
{
    constexpr uint32_t AU = pmask(PAS, NP);
    constexpr uint32_t BU = pmask(PBS, NP);
    constexpr int NC     = K / 64;
    constexpr int PLANEB = 8192;
    constexpr int STAGEB = 8 * PLANEB;

    extern __shared__ char smem[];
    const uint32_t sbase = smem_u32(smem);
    const int tid  = threadIdx.x;
    const int lane = tid & 31;
    const int wid  = tid >> 5;
    const int wm   = wid >> 2;
    const int wn   = wid & 3;
    const int n0 = blockIdx.x * 128;
    const int m0 = blockIdx.y * 128;

    const int8_t* pl[8];
    pl[0] = a0 + (size_t)m0 * K; pl[1] = a1 + (size_t)m0 * K;
    pl[2] = a2 + (size_t)m0 * K; pl[3] = a3 + (size_t)m0 * K;
    pl[4] = b0 + (size_t)n0 * K; pl[5] = b1 + (size_t)n0 * K;
    pl[6] = b2 + (size_t)n0 * K; pl[7] = b3 + (size_t)n0 * K;

    int acc[2][4][4][4];
#pragma unroll
    for (int g = 0; g < 2; ++g)
#pragma unroll
        for (int i = 0; i < 4; ++i)
#pragma unroll
            for (int j = 0; j < 4; ++j)
#pragma unroll
                for (int r = 0; r < 4; ++r) acc[g][i][j][r] = 0;

    auto load_stage = [&](int c, int buf) {
        const uint32_t base = sbase + buf * STAGEB;
#pragma unroll
        for (int P = 0; P < 8; ++P) {
            const bool used = ((P < 4 ? (AU >> P) : (BU >> (P - 4))) & 1) != 0;
            if (!used) continue;
#pragma unroll
            for (int it = 0; it < 2; ++it) {
                const int id = it * 256 + tid;
                const int row = id >> 2, c16 = id & 3;
                cp_async16(base + P * PLANEB + sw64(row, c16),
                           pl[P] + (size_t)row * K + c * 64 + c16 * 16);
            }
        }
        cp_commit();
    };

    const int aR  = (lane & 7) + ((lane >> 3) & 1) * 8;
    const int aCs = lane >> 4;
    const int bN  = (lane & 7) + (lane >> 4) * 8;
    const int bCs = (lane >> 3) & 1;

    auto compute = [&](int buf) {
        const uint32_t base = sbase + buf * STAGEB;
#pragma unroll
        for (int pi = 0; pi < NP; ++pi) {
            const int pa = (PAS >> (4 * pi)) & 15;
            const int pb = (PBS >> (4 * pi)) & 15;
            const int gg = (GRS >> (4 * pi)) & 15;
            const uint32_t Ab = base + pa * PLANEB;
            const uint32_t Bb = base + (4 + pb) * PLANEB;
#pragma unroll
            for (int ks = 0; ks < 2; ++ks) {
                uint32_t af[4][4];
#pragma unroll
                for (int mf = 0; mf < 4; ++mf)
                    ldsm4(af[mf], Ab + sw64(wm * 64 + mf * 16 + aR, ks * 2 + aCs));
                uint32_t bf[2][4];
#pragma unroll
                for (int nh = 0; nh < 2; ++nh)
                    ldsm4(bf[nh], Bb + sw64(wn * 32 + nh * 16 + bN, ks * 2 + bCs));
#pragma unroll
                for (int mf = 0; mf < 4; ++mf)
#pragma unroll
                    for (int nf = 0; nf < 4; ++nf)
                        mma_s8(acc[gg][mf][nf], af[mf], bf[nf >> 1] + (nf & 1) * 2);
            }
        }
    };

    load_stage(0, 0);
    for (int c = 0; c < NC; ++c) {
        if (c + 1 < NC) { load_stage(c + 1, (c + 1) & 1); cp_wait<1>(); }
        else            { cp_wait<0>(); }
        __syncthreads();
        compute(c & 1);
        __syncthreads();
    }

    const int gr = lane >> 2;
    const int gc = (lane & 3) * 2;
#pragma unroll
    for (int mf = 0; mf < 4; ++mf) {
        const int row0 = m0 + wm * 64 + mf * 16 + gr;
#pragma unroll
        for (int nf = 0; nf < 4; ++nf) {
            const int col = n0 + wn * 32 + nf * 8 + gc;
            float r[4];
#pragma unroll
            for (int q = 0; q < 4; ++q)
                r[q] = (float)acc[0][mf][nf][q] * sc0 + (float)acc[1][mf][nf][q] * sc1;
            float* o0 = &Cout[(size_t)row0 * NOUT + col];
            float* o1 = &Cout[(size_t)(row0 + 8) * NOUT + col];
            if (ACCUM) {
                float2 e0 = *reinterpret_cast<float2*>(o0);
                float2 e1 = *reinterpret_cast<float2*>(o1);
                *reinterpret_cast<float2*>(o0) = make_float2(e0.x + r[0], e0.y + r[1]);
                *reinterpret_cast<float2*>(o1) = make_float2(e1.x + r[2], e1.y + r[3]);
            } else {
                const float2 bv = *reinterpret_cast<const float2*>(&bias[col]);
                *reinterpret_cast<float2*>(o0) = make_float2(r[0] + bv.x, r[1] + bv.y);
                *reinterpret_cast<float2*>(o1) = make_float2(r[2] + bv.x, r[3] + bv.y);
            }
        }
    }
}

// ---------------------------------------------------------------------------
// BN stats + fused BN/LIF
// ---------------------------------------------------------------------------
template <int NN>
__global__ __launch_bounds__(256) void stat_partial(const float* __restrict__ y,
                                                    float* __restrict__ ps,
                                                    float* __restrict__ pq)
{
    const int col = blockIdx.x * 256 + threadIdx.x;
    const size_t base = (size_t)blockIdx.y * 1024 * NN + col;
    float s = 0.f, q = 0.f;
#pragma unroll 8
    for (int r = 0; r < 1024; ++r) {
        float v = y[base + (size_t)r * NN];
        s += v;
        q += v * v;
    }
    ps[blockIdx.y * NN + col] = s;
    pq[blockIdx.y * NN + col] = q;
}

__global__ void finalize_stats(const float* __restrict__ psum, const float* __restrict__ psq,
                               const float* __restrict__ gamma,
                               float* __restrict__ meanOut, float* __restrict__ scOut, int N)
{
    int n = blockIdx.x * blockDim.x + threadIdx.x;
    if (n >= N) return;
    double s = 0.0, q = 0.0;
    for (int r = 0; r < RB_; ++r) {
        s += (double)psum[(size_t)r * N + n];
        q += (double)psq[(size_t)r * N + n];
    }
    const double inv = 1.0 / (double)M_;
    double dm = s * inv;
    meanOut[n] = (float)dm;
    float var  = (float)(q * inv - dm * dm);
    scOut[n]   = gamma[n] / sqrtf(var + EPS_);
}

template <int CH, bool RES, typename OutT>
__global__ __launch_bounds__(256) void bn_lif_kernel(
    const float* __restrict__ y, const float* __restrict__ mean,
    const float* __restrict__ sc, const float* __restrict__ beta,
    const float* __restrict__ resid, OutT* __restrict__ outp)
{
    const long long idx = (long long)blockIdx.x * blockDim.x + threadIdx.x;
    if (idx >= (long long)ROWS_ * CH) return;
    const int h = (int)(idx & (CH - 1));
    const float m = mean[h], s = sc[h], bt = beta[h];
    const size_t base = (size_t)idx;
    const size_t stride = (size_t)ROWS_ * CH;
    float v = 0.f;
#pragma unroll
    for (int t = 0; t < T_; ++t) {
        const size_t off = base + (size_t)t * stride;
        float yv = (y[off] - m) * s + bt;
        v = v + (yv - v) * 0.5f;
        float sp = (v >= 1.0f) ? 1.0f : 0.0f;
        float o = RES ? (sp + resid[off]) : sp;
        outp[off] = (OutT)o;
        v = (v >= 1.0f) ? 0.0f : v;
    }
}

// ---------------------------------------------------------------------------
extern "C" void kernel_launch(void* const* d_in, const int* in_sizes, int n_in,
                              void* d_out, int out_size)
{
    (void)in_sizes; (void)n_in; (void)out_size;
    const float* x     = (const float*)d_in[0];
    const float* fc1_w = (const float*)d_in[1];
    const float* fc1_b = (const float*)d_in[2];
    const float* bn1_g = (const float*)d_in[3];
    const float* bn1_b = (const float*)d_in[4];
    const float* fc2_w = (const float*)d_in[5];
    const float* fc2_b = (const float*)d_in[6];
    const float* bn2_g = (const float*)d_in[7];
    const float* bn2_b = (const float*)d_in[8];
    float* out = (float*)d_out;

    float *y, *z, *p1s, *p1q, *p2s, *p2q, *mean1, *sc1, *mean2, *sc2;
    int8_t *sp, *w2p;
    cudaGetSymbolAddress((void**)&y, g_y);
    cudaGetSymbolAddress((void**)&z, g_z);
    cudaGetSymbolAddress((void**)&sp, g_sp);
    cudaGetSymbolAddress((void**)&w2p, g_w2p);
    cudaGetSymbolAddress((void**)&p1s, g_p1s);
    cudaGetSymbolAddress((void**)&p1q, g_p1q);
    cudaGetSymbolAddress((void**)&p2s, g_p2s);
    cudaGetSymbolAddress((void**)&p2q, g_p2q);
    cudaGetSymbolAddress((void**)&mean1, g_mean1);
    cudaGetSymbolAddress((void**)&sc1, g_sc1);
    cudaGetSymbolAddress((void**)&mean2, g_mean2);
    cudaGetSymbolAddress((void**)&sc2, g_sc2);

    const size_t nW2 = (size_t)C_ * H_;
    int8_t* w2l[4];
    for (int i = 0; i < 4; ++i) w2l[i] = w2p + i * nW2;

    // fc2 pass kernels: pairs (spike, w digit j) at scales 2^(-7-8j)
    auto k_f2p0 = gemm_i8<0x00u, 0x10u, 0x10u, 2, H_, C_, false>;  // j=0,1
    auto k_f2p1 = gemm_i8<0x00u, 0x32u, 0x10u, 2, H_, C_, true>;   // j=2,3

    constexpr int SMEM_I8 = 2 * 8 * 8192;          // 131072
    cudaFuncSetAttribute(k_f2p0, cudaFuncAttributeMaxDynamicSharedMemorySize, SMEM_I8);
    cudaFuncSetAttribute(k_f2p1, cudaFuncAttributeMaxDynamicSharedMemorySize, SMEM_I8);

    // digitize w2 (exact: |w2| < 1, scale 2^31)
    digitize_kernel<<<512, 256>>>(fc2_w, nW2, 2147483648.0f,
                                  w2l[0], w2l[1], w2l[2], w2l[3]);

    // fc1 -> y (fp32, reference-correlated rounding; Round-1 body)
    sgemm_f32<C_, H_><<<dim3(H_ / 128, M_ / 128), 256>>>(x, fc1_w, fc1_b, y);

    // BN1 + LIF1 -> spikes (s8 exact)
    stat_partial<H_><<<dim3(H_ / 256, RB_), 256>>>(y, p1s, p1q);
    finalize_stats<<<H_ / 256, 256>>>(p1s, p1q, bn1_g, mean1, sc1, H_);
    bn_lif_kernel<H_, false, int8_t><<<(ROWS_ * H_) / 256, 256>>>(
        y, mean1, sc1, bn1_b, nullptr, sp);

    // fc2 -> z (exact IMMA, two passes)
    const dim3 g2(C_ / 128, M_ / 128);
    k_f2p0<<<g2, 256, SMEM_I8>>>(sp, sp, sp, sp, w2l[0], w2l[1], w2l[2], w2l[3],
                                 fc2_b, z, 0x1p-7f, 0x1p-15f);
    k_f2p1<<<g2, 256, SMEM_I8>>>(sp, sp, sp, sp, w2l[0], w2l[1], w2l[2], w2l[3],
                                 fc2_b, z, 0x1p-23f, 0x1p-31f);

    // BN2 + LIF2 + residual -> out
    stat_partial<C_><<<dim3(C_ / 256, RB_), 256>>>(z, p2s, p2q);
    finalize_stats<<<C_ / 256, 256>>>(p2s, p2q, bn2_g, mean2, sc2, C_);
    bn_lif_kernel<C_, true, float><<<(ROWS_ * C_) / 256, 256>>>(
        z, mean2, sc2, bn2_b, x, out);
}

// round 17
// speedup vs baseline: 1.6197x; 1.6197x over previous
#include <cuda_runtime.h>
#include <cuda_bf16.h>
#include <cstdint>
#include <cstddef>

// ===========================================================================
// SpikingMLP hybrid v2: fc1 = fp32 FFMA GEMM (Round-1 body, rounding
// correlated with the JAX reference -> l1 spikes match R1 exactly);
// fc2 = bf16 HMMA, A = spikes (exact in bf16), W2 = exact 3-way bf16 split,
// main product drained per k16 (R6 structure). T=4 B=16 N=1024 C=512 H=2048.
// ===========================================================================

namespace {
constexpr int T_ = 4, B_ = 16, N_ = 1024, C_ = 512, H_ = 2048;
constexpr int M_    = T_ * B_ * N_;   // 65536
constexpr int ROWS_ = B_ * N_;        // 16384
constexpr int RB_   = 64;
constexpr float EPS_ = 1e-5f;
}

#define SWZ(o) ((o) ^ (((o) >> 3) & 0x70))

// ----------------------------- scratch ------------------------------------
__device__ __align__(256) float          g_y[(size_t)M_ * H_];
__device__ __align__(256) float          g_z[(size_t)M_ * C_];
__device__ __align__(256) __nv_bfloat16  g_sb[(size_t)M_ * H_];   // spikes bf16
__device__ __align__(256) __nv_bfloat16  g_w20[C_ * H_], g_w21[C_ * H_], g_w22[C_ * H_];
__device__ float g_p1s[RB_ * H_], g_p1q[RB_ * H_];
__device__ float g_p2s[RB_ * C_], g_p2q[RB_ * C_];
__device__ float g_mean1[H_], g_sc1[H_], g_mean2[C_], g_sc2[C_];

// ----------------------------- PTX helpers --------------------------------
__device__ __forceinline__ uint32_t smem_u32(const void* p) {
    uint32_t a;
    asm("{ .reg .u64 t; cvta.to.shared.u64 t, %1; cvt.u32.u64 %0, t; }" : "=r"(a) : "l"(p));
    return a;
}
__device__ __forceinline__ void cp_async16(uint32_t s, const void* g) {
    asm volatile("cp.async.cg.shared.global [%0], [%1], 16;" :: "r"(s), "l"(g) : "memory");
}
__device__ __forceinline__ void cp_commit() {
    asm volatile("cp.async.commit_group;" ::: "memory");
}
template <int N_PEND>
__device__ __forceinline__ void cp_wait() {
    asm volatile("cp.async.wait_group %0;" :: "n"(N_PEND) : "memory");
}
__device__ __forceinline__ void ldsm4(uint32_t* r, uint32_t a) {
    asm volatile("ldmatrix.sync.aligned.m8n8.x4.shared.b16 {%0,%1,%2,%3}, [%4];"
                 : "=r"(r[0]), "=r"(r[1]), "=r"(r[2]), "=r"(r[3]) : "r"(a) : "memory");
}
__device__ __forceinline__ void mma16816(float* c, const uint32_t* a, const uint32_t* b) {
    asm volatile(
        "mma.sync.aligned.m16n8k16.row.col.f32.bf16.bf16.f32 "
        "{%0,%1,%2,%3}, {%4,%5,%6,%7}, {%8,%9}, {%0,%1,%2,%3};"
        : "+f"(c[0]), "+f"(c[1]), "+f"(c[2]), "+f"(c[3])
        : "r"(a[0]), "r"(a[1]), "r"(a[2]), "r"(a[3]), "r"(b[0]), "r"(b[1]));
}

// ---------------------------------------------------------------------------
// fp32 SGEMM (fc1) — Round-1's exact body (reference-correlated rounding).
// ---------------------------------------------------------------------------
template <int K, int NOUT>
__global__ __launch_bounds__(256) void sgemm_f32(
    const float* __restrict__ A, const float* __restrict__ Bw,
    const float* __restrict__ bias, float* __restrict__ Cout)
{
    __shared__ float As[16][128];
    __shared__ float Bs[16][128];

    const int tid = threadIdx.x;
    const int tx = tid & 15;
    const int ty = tid >> 4;
    const int n0 = blockIdx.x * 128;
    const int m0 = blockIdx.y * 128;

    const float* Ap = A + (size_t)m0 * K;
    const float* Bp = Bw + (size_t)n0 * K;

    float acc[8][8];
#pragma unroll
    for (int i = 0; i < 8; ++i)
#pragma unroll
        for (int j = 0; j < 8; ++j) acc[i][j] = 0.f;

    for (int k0 = 0; k0 < K; k0 += 16) {
#pragma unroll
        for (int it = 0; it < 2; ++it) {
            int idx = tid + it * 256;
            int row = idx >> 2;
            int kq  = (idx & 3) << 2;
            float4 av = *reinterpret_cast<const float4*>(Ap + (size_t)row * K + k0 + kq);
            As[kq + 0][row] = av.x; As[kq + 1][row] = av.y;
            As[kq + 2][row] = av.z; As[kq + 3][row] = av.w;
            float4 bv = *reinterpret_cast<const float4*>(Bp + (size_t)row * K + k0 + kq);
            Bs[kq + 0][row] = bv.x; Bs[kq + 1][row] = bv.y;
            Bs[kq + 2][row] = bv.z; Bs[kq + 3][row] = bv.w;
        }
        __syncthreads();
#pragma unroll
        for (int k = 0; k < 16; ++k) {
            float a[8], b[8];
            *reinterpret_cast<float4*>(a)     = *reinterpret_cast<const float4*>(&As[k][ty * 8]);
            *reinterpret_cast<float4*>(a + 4) = *reinterpret_cast<const float4*>(&As[k][ty * 8 + 4]);
            *reinterpret_cast<float4*>(b)     = *reinterpret_cast<const float4*>(&Bs[k][tx * 8]);
            *reinterpret_cast<float4*>(b + 4) = *reinterpret_cast<const float4*>(&Bs[k][tx * 8 + 4]);
#pragma unroll
            for (int i = 0; i < 8; ++i)
#pragma unroll
                for (int j = 0; j < 8; ++j)
                    acc[i][j] += a[i] * b[j];
        }
        __syncthreads();
    }

    float bvals[8];
#pragma unroll
    for (int j = 0; j < 8; ++j) bvals[j] = bias[n0 + tx * 8 + j];

#pragma unroll
    for (int i = 0; i < 8; ++i) {
        float rowv[8];
#pragma unroll
        for (int j = 0; j < 8; ++j) rowv[j] = acc[i][j] + bvals[j];
        float* outp = Cout + (size_t)(m0 + ty * 8 + i) * NOUT + n0 + tx * 8;
        *reinterpret_cast<float4*>(outp)     = make_float4(rowv[0], rowv[1], rowv[2], rowv[3]);
        *reinterpret_cast<float4*>(outp + 4) = make_float4(rowv[4], rowv[5], rowv[6], rowv[7]);
    }
}

// ---------------------------------------------------------------------------
// Exact 3-way bf16 split of w2.
// ---------------------------------------------------------------------------
__global__ void split3_kernel(const float4* __restrict__ src, size_t n4,
                              uint32_t* __restrict__ d0, uint32_t* __restrict__ d1,
                              uint32_t* __restrict__ d2)
{
    for (size_t i = (size_t)blockIdx.x * blockDim.x + threadIdx.x; i < n4;
         i += (size_t)gridDim.x * blockDim.x) {
        float4 v = src[i];
        float vv[4] = {v.x, v.y, v.z, v.w};
        uint16_t h0[4], h1[4], h2[4];
#pragma unroll
        for (int j = 0; j < 4; ++j) {
            __nv_bfloat16 b0 = __float2bfloat16(vv[j]);
            float r = vv[j] - __bfloat162float(b0);
            __nv_bfloat16 b1 = __float2bfloat16(r);
            float r2 = r - __bfloat162float(b1);
            __nv_bfloat16 b2 = __float2bfloat16(r2);
            h0[j] = __bfloat16_as_ushort(b0);
            h1[j] = __bfloat16_as_ushort(b1);
            h2[j] = __bfloat16_as_ushort(b2);
        }
        d0[2 * i]     = (uint32_t)h0[0] | ((uint32_t)h0[1] << 16);
        d0[2 * i + 1] = (uint32_t)h0[2] | ((uint32_t)h0[3] << 16);
        d1[2 * i]     = (uint32_t)h1[0] | ((uint32_t)h1[1] << 16);
        d1[2 * i + 1] = (uint32_t)h1[2] | ((uint32_t)h1[3] << 16);
        d2[2 * i]     = (uint32_t)h2[0] | ((uint32_t)h2[1] << 16);
        d2[2 * i + 1] = (uint32_t)h2[2] | ((uint32_t)h2[3] << 16);
    }
}

// ---------------------------------------------------------------------------
// bf16 HMMA GEMM (fc2): A = spikes (exact bf16), B = w2 in 3 split planes.
// Correction products (0,b1),(0,b2) chained in the MMA accumulator first;
// main product (0,b0) drained into an RN fp32 sum after every k16 step.
// CTA 128x128, K-chunk 64, 8 warps (2x4), cp.async double buffer, XOR swizzle.
// ---------------------------------------------------------------------------
template <int K, int NOUT>
__global__ __launch_bounds__(256, 1) void gemm_bf16_fc2(
    const __nv_bfloat16* __restrict__ a0,
    const __nv_bfloat16* __restrict__ b0, const __nv_bfloat16* __restrict__ b1,
    const __nv_bfloat16* __restrict__ b2,
    const float* __restrict__ bias, float* __restrict__ Cout)
{
    constexpr int NPART  = 4;             // A, B0, B1, B2
    constexpr int NC     = K / 64;
    constexpr int KQ     = K / 8;
    constexpr int TILEB  = 16384;
    constexpr int STAGEB = NPART * TILEB;

    extern __shared__ char smem[];
    const uint32_t sbase = smem_u32(smem);
    const int tid  = threadIdx.x;
    const int lane = tid & 31;
    const int wid  = tid >> 5;
    const int wm   = wid >> 2;
    const int wn   = wid & 3;
    const int n0 = blockIdx.x * 128;
    const int m0 = blockIdx.y * 128;

    const uint4* pg[NPART];
    pg[0] = reinterpret_cast<const uint4*>(a0) + (size_t)m0 * KQ;
    pg[1] = reinterpret_cast<const uint4*>(b0) + (size_t)n0 * KQ;
    pg[2] = reinterpret_cast<const uint4*>(b1) + (size_t)n0 * KQ;
    pg[3] = reinterpret_cast<const uint4*>(b2) + (size_t)n0 * KQ;

    float acc[4][4][4];
    float sum[4][4][4];
#pragma unroll
    for (int i = 0; i < 4; ++i)
#pragma unroll
        for (int j = 0; j < 4; ++j)
#pragma unroll
            for (int r = 0; r < 4; ++r) { acc[i][j][r] = 0.f; sum[i][j][r] = 0.f; }

    auto load_stage = [&](int c, int buf) {
        const uint32_t base = sbase + buf * STAGEB;
#pragma unroll
        for (int i = 0; i < NPART * 4; ++i) {
            const int part   = i >> 2;
            const int within = (i & 3) * 256 + tid;
            const int row = within >> 3, q = within & 7;
            uint32_t saddr = base + part * TILEB + SWZ(row * 128 + q * 16);
            cp_async16(saddr, pg[part] + (size_t)row * KQ + c * 8 + q);
        }
        cp_commit();
    };

    const int aR = (lane & 7) + ((lane >> 3) & 1) * 8;
    const int aK = (lane >> 4) * 8;
    const int bN = (lane & 7) + (lane >> 4) * 8;
    const int bK = ((lane >> 3) & 1) * 8;

    auto compute = [&](int buf) {
        const uint32_t base = sbase + buf * STAGEB;
        // corrections (0,b1),(0,b2): chained (magnitude <= 2^-9)
#pragma unroll
        for (int pb = 1; pb < 3; ++pb) {
            const uint32_t Ab = base;
            const uint32_t Bb = base + (1 + pb) * TILEB;
#pragma unroll
            for (int k16 = 0; k16 < 4; ++k16) {
                uint32_t af[4][4];
#pragma unroll
                for (int mf = 0; mf < 4; ++mf) {
                    uint32_t off = (uint32_t)(wm * 64 + mf * 16 + aR) * 128
                                 + (uint32_t)(k16 * 16 + aK) * 2;
                    ldsm4(af[mf], Ab + SWZ(off));
                }
                uint32_t bf[2][4];
#pragma unroll
                for (int nh = 0; nh < 2; ++nh) {
                    uint32_t off = (uint32_t)(wn * 32 + nh * 16 + bN) * 128
                                 + (uint32_t)(k16 * 16 + bK) * 2;
                    ldsm4(bf[nh], Bb + SWZ(off));
                }
#pragma unroll
                for (int mf = 0; mf < 4; ++mf)
#pragma unroll
                    for (int nf = 0; nf < 4; ++nf)
                        mma16816(acc[mf][nf], af[mf], bf[nf >> 1] + (nf & 1) * 2);
            }
        }
        // main (0,b0): drain after every k16
        {
            const uint32_t Ab = base;
            const uint32_t Bb = base + 1 * TILEB;
#pragma unroll
            for (int k16 = 0; k16 < 4; ++k16) {
                uint32_t af[4][4];
#pragma unroll
                for (int mf = 0; mf < 4; ++mf) {
                    uint32_t off = (uint32_t)(wm * 64 + mf * 16 + aR) * 128
                                 + (uint32_t)(k16 * 16 + aK) * 2;
                    ldsm4(af[mf], Ab + SWZ(off));
                }
                uint32_t bf[2][4];
#pragma unroll
                for (int nh = 0; nh < 2; ++nh) {
                    uint32_t off = (uint32_t)(wn * 32 + nh * 16 + bN) * 128
                                 + (uint32_t)(k16 * 16 + bK) * 2;
                    ldsm4(bf[nh], Bb + SWZ(off));
                }
#pragma unroll
                for (int mf = 0; mf < 4; ++mf)
#pragma unroll
                    for (int nf = 0; nf < 4; ++nf)
                        mma16816(acc[mf][nf], af[mf], bf[nf >> 1] + (nf & 1) * 2);
#pragma unroll
                for (int mf = 0; mf < 4; ++mf)
#pragma unroll
                    for (int nf = 0; nf < 4; ++nf)
#pragma unroll
                        for (int r = 0; r < 4; ++r) {
                            sum[mf][nf][r] += acc[mf][nf][r];
                            acc[mf][nf][r] = 0.f;
                        }
            }
        }
    };

    load_stage(0, 0);
    for (int c = 0; c < NC; ++c) {
        if (c + 1 < NC) { load_stage(c + 1, (c + 1) & 1); cp_wait<1>(); }
        else            { cp_wait<0>(); }
        __syncthreads();
        compute(c & 1);
        __syncthreads();
    }

    const int gr = lane >> 2;
    const int gc = (lane & 3) * 2;
#pragma unroll
    for (int mf = 0; mf < 4; ++mf) {
        const int row0 = m0 + wm * 64 + mf * 16 + gr;
#pragma unroll
        for (int nf = 0; nf < 4; ++nf) {
            const int col = n0 + wn * 32 + nf * 8 + gc;
            const float2 bv = *reinterpret_cast<const float2*>(&bias[col]);
            float2 o0 = make_float2(sum[mf][nf][0] + bv.x, sum[mf][nf][1] + bv.y);
            float2 o1 = make_float2(sum[mf][nf][2] + bv.x, sum[mf][nf][3] + bv.y);
            *reinterpret_cast<float2*>(&Cout[(size_t)row0 * NOUT + col]) = o0;
            *reinterpret_cast<float2*>(&Cout[(size_t)(row0 + 8) * NOUT + col]) = o1;
        }
    }
}

// ---------------------------------------------------------------------------
// BN stats + fused BN/LIF
// ---------------------------------------------------------------------------
template <int NN>
__global__ __launch_bounds__(256) void stat_partial(const float* __restrict__ y,
                                                    float* __restrict__ ps,
                                                    float* __restrict__ pq)
{
    const int col = blockIdx.x * 256 + threadIdx.x;
    const size_t base = (size_t)blockIdx.y * 1024 * NN + col;
    float s = 0.f, q = 0.f;
#pragma unroll 8
    for (int r = 0; r < 1024; ++r) {
        float v = y[base + (size_t)r * NN];
        s += v;
        q += v * v;
    }
    ps[blockIdx.y * NN + col] = s;
    pq[blockIdx.y * NN + col] = q;
}

__global__ void finalize_stats(const float* __restrict__ psum, const float* __restrict__ psq,
                               const float* __restrict__ gamma,
                               float* __restrict__ meanOut, float* __restrict__ scOut, int N)
{
    int n = blockIdx.x * blockDim.x + threadIdx.x;
    if (n >= N) return;
    double s = 0.0, q = 0.0;
    for (int r = 0; r < RB_; ++r) {
        s += (double)psum[(size_t)r * N + n];
        q += (double)psq[(size_t)r * N + n];
    }
    const double inv = 1.0 / (double)M_;
    double dm = s * inv;
    meanOut[n] = (float)dm;
    float var  = (float)(q * inv - dm * dm);
    scOut[n]   = gamma[n] / sqrtf(var + EPS_);
}

template <int CH, bool RES, typename OutT>
__global__ __launch_bounds__(256) void bn_lif_kernel(
    const float* __restrict__ y, const float* __restrict__ mean,
    const float* __restrict__ sc, const float* __restrict__ beta,
    const float* __restrict__ resid, OutT* __restrict__ outp)
{
    const long long idx = (long long)blockIdx.x * blockDim.x + threadIdx.x;
    if (idx >= (long long)ROWS_ * CH) return;
    const int h = (int)(idx & (CH - 1));
    const float m = mean[h], s = sc[h], bt = beta[h];
    const size_t base = (size_t)idx;
    const size_t stride = (size_t)ROWS_ * CH;
    float v = 0.f;
#pragma unroll
    for (int t = 0; t < T_; ++t) {
        const size_t off = base + (size_t)t * stride;
        float yv = (y[off] - m) * s + bt;
        v = v + (yv - v) * 0.5f;
        float sp = (v >= 1.0f) ? 1.0f : 0.0f;
        float o = RES ? (sp + resid[off]) : sp;
        outp[off] = (OutT)o;
        v = (v >= 1.0f) ? 0.0f : v;
    }
}

// ---------------------------------------------------------------------------
extern "C" void kernel_launch(void* const* d_in, const int* in_sizes, int n_in,
                              void* d_out, int out_size)
{
    (void)in_sizes; (void)n_in; (void)out_size;
    const float* x     = (const float*)d_in[0];
    const float* fc1_w = (const float*)d_in[1];
    const float* fc1_b = (const float*)d_in[2];
    const float* bn1_g = (const float*)d_in[3];
    const float* bn1_b = (const float*)d_in[4];
    const float* fc2_w = (const float*)d_in[5];
    const float* fc2_b = (const float*)d_in[6];
    const float* bn2_g = (const float*)d_in[7];
    const float* bn2_b = (const float*)d_in[8];
    float* out = (float*)d_out;

    float *y, *z, *p1s, *p1q, *p2s, *p2q, *mean1, *sc1, *mean2, *sc2;
    __nv_bfloat16 *sbf, *w20, *w21, *w22;
    cudaGetSymbolAddress((void**)&y, g_y);
    cudaGetSymbolAddress((void**)&z, g_z);
    cudaGetSymbolAddress((void**)&sbf, g_sb);
    cudaGetSymbolAddress((void**)&w20, g_w20);
    cudaGetSymbolAddress((void**)&w21, g_w21);
    cudaGetSymbolAddress((void**)&w22, g_w22);
    cudaGetSymbolAddress((void**)&p1s, g_p1s);
    cudaGetSymbolAddress((void**)&p1q, g_p1q);
    cudaGetSymbolAddress((void**)&p2s, g_p2s);
    cudaGetSymbolAddress((void**)&p2q, g_p2q);
    cudaGetSymbolAddress((void**)&mean1, g_mean1);
    cudaGetSymbolAddress((void**)&sc1, g_sc1);
    cudaGetSymbolAddress((void**)&mean2, g_mean2);
    cudaGetSymbolAddress((void**)&sc2, g_sc2);

    constexpr int SMEM_FC2 = 2 * 4 * 16384;   // 131072
    cudaFuncSetAttribute(gemm_bf16_fc2<H_, C_>,
                         cudaFuncAttributeMaxDynamicSharedMemorySize, SMEM_FC2);

    // split w2 into 3 exact bf16 planes
    split3_kernel<<<512, 256>>>((const float4*)fc2_w, (size_t)C_ * H_ / 4,
                                (uint32_t*)w20, (uint32_t*)w21, (uint32_t*)w22);

    // fc1 -> y (fp32, reference-correlated rounding)
    sgemm_f32<C_, H_><<<dim3(H_ / 128, M_ / 128), 256>>>(x, fc1_w, fc1_b, y);

    // BN1 + LIF1 -> spikes (bf16, exact)
    stat_partial<H_><<<dim3(H_ / 256, RB_), 256>>>(y, p1s, p1q);
    finalize_stats<<<H_ / 256, 256>>>(p1s, p1q, bn1_g, mean1, sc1, H_);
    bn_lif_kernel<H_, false, __nv_bfloat16><<<(ROWS_ * H_) / 256, 256>>>(
        y, mean1, sc1, bn1_b, nullptr, sbf);

    // fc2 -> z (bf16 HMMA, exact A, split W, drained main product)
    gemm_bf16_fc2<H_, C_><<<dim3(C_ / 128, M_ / 128), 256, SMEM_FC2>>>(
        sbf, w20, w21, w22, fc2_b, z);

    // BN2 + LIF2 + residual -> out
    stat_partial<C_><<<dim3(C_ / 256, RB_), 256>>>(z, p2s, p2q);
    finalize_stats<<<C_ / 256, 256>>>(p2s, p2q, bn2_g, mean2, sc2, C_);
    bn_lif_kernel<C_, true, float><<<(ROWS_ * C_) / 256, 256>>>(
        z, mean2, sc2, bn2_b, x, out);
}